// round 9
// baseline (speedup 1.0000x reference)
#include <cuda_runtime.h>

// ---------------- problem constants ----------------
#define NPC   16
#define FBP   8
#define CH    128
#define HH    96
#define H0    94          // after piece conv
#define H1    92          // after conv #1
#define H2    90          // after conv #2
#define FEAT  (CH*H2*H2)  // 1,036,800
#define OUTD  256
#define GCHUNK 4096
#define NBLK  ((FEAT + GCHUNK - 1) / GCHUNK)   // 254

typedef unsigned long long ull;

// ---------------- scratch (no allocation allowed) ----------------
__device__ float g_y0[CH * H0 * H0];
__device__ float g_y1[CH * H1 * H1];
__device__ float g_y2[CH * H2 * H2];
__device__ float g_part[NBLK * OUTD];

// ---------------- packed f32x2 helpers (sm_103a) ----------------
__device__ __forceinline__ ull pk(float lo, float hi) {
    ull r;
    asm("mov.b64 %0, {%1, %2};" : "=l"(r) : "f"(lo), "f"(hi));
    return r;
}
__device__ __forceinline__ void fma2(ull &d, ull a, ull b) {
    asm("fma.rn.f32x2 %0, %1, %2, %0;" : "+l"(d) : "l"(a), "l"(b));
}
__device__ __forceinline__ float2 up(ull v) {
    float x, y;
    asm("mov.b64 {%0, %1}, %2;" : "=f"(x), "=f"(y) : "l"(v));
    return make_float2(x, y);
}

// ---------------- kernel 1: grouped piece conv + bias + relu ----------------
__global__ void piece_conv(const int* __restrict__ x, const float* __restrict__ cw,
                           const float* __restrict__ cb, float* __restrict__ y0) {
    __shared__ float sw[72];
    __shared__ float sb[8];
    int p = blockIdx.y;
    if (threadIdx.x < 72) sw[threadIdx.x] = cw[p * 72 + threadIdx.x];
    if (threadIdx.x < 8)  sb[threadIdx.x] = cb[p * 8 + threadIdx.x];
    __syncthreads();
    int pix = blockIdx.x * blockDim.x + threadIdx.x;
    if (pix >= H0 * H0) return;
    int i = pix / H0, j = pix % H0;
    float acc[FBP];
#pragma unroll
    for (int f = 0; f < FBP; f++) acc[f] = sb[f];
#pragma unroll
    for (int di = 0; di < 3; di++) {
#pragma unroll
        for (int dj = 0; dj < 3; dj++) {
            int v = x[(i + di) * HH + (j + dj)];
            if (v == p) {
#pragma unroll
                for (int f = 0; f < FBP; f++) acc[f] += sw[f * 9 + di * 3 + dj];
            }
        }
    }
#pragma unroll
    for (int f = 0; f < FBP; f++)
        y0[(p * FBP + f) * (H0 * H0) + pix] = fmaxf(acc[f], 0.f);
}

// ---------------- conv 3x3 VALID + bias + relu, templated Cout/block ----------------
// NCR = Couts per thread; block covers 32*NCR Couts, tile 4 rows x 16 cols.
// Row-paired f32x2 accumulators; zero pack instructions in inner loop;
// software-pipelined register prefetch of next cib's weights + x.
#define CI_T 4
#define WS_STRIDE 37
template <int NCR>
__global__ void __launch_bounds__(256, 2) conv3x3(
    const float* __restrict__ in, const float* __restrict__ w,
    const float* __restrict__ b, float* __restrict__ out,
    int Hin, int Hout, int zbase) {
    constexpr int COPB = 32 * NCR;
    constexpr int WTOT = COPB * 36;
    constexpr int WPT  = (WTOT + 255) / 256;
    __shared__ __align__(16) float2 ws[COPB * WS_STRIDE];
    __shared__ __align__(16) float2 xp[CI_T * 4 * 18];

    int t = threadIdx.x;
    int co_g = t >> 3;
    int pg   = t & 7;
    int rp   = pg & 1;
    int cg   = pg >> 1;
    int i0 = blockIdx.y * 4, j0 = blockIdx.x * 16;
    int zc = zbase + blockIdx.z * COPB;

    int wg_off[WPT], ws_off[WPT];
    bool wok[WPT];
#pragma unroll
    for (int k = 0; k < WPT; k++) {
        int idx = t + 256 * k;
        wok[k] = (idx < WTOT);
        int ii = wok[k] ? idx : 0;
        int lc = ii / 36, r = ii - lc * 36;
        int ci = r / 9,  d = r - ci * 9;
        wg_off[k] = ((zc + lc) * CH + ci) * 9 + d;
        ws_off[k] = lc * WS_STRIDE + r;
    }
    int xg_off[2], xci[2];
    unsigned char xva[2], xvb[2];
#pragma unroll
    for (int e = 0; e < 2; e++) {
        int idx = t + 256 * e;
        int ci = idx / 72, rem = idx - ci * 72;
        int rr = rem / 18, c = rem - rr * 18;
        int gi = i0 + rr, gj = j0 + c;
        xci[e] = ci;
        xg_off[e] = gi * Hin + gj;
        xva[e] = (gi < Hin && gj < Hin);
        xvb[e] = (gi + 2 < Hin && gj < Hin);
    }

    float  wreg[WPT];
    float2 xreg[2];
#pragma unroll
    for (int k = 0; k < WPT; k++)
        wreg[k] = wok[k] ? __ldg(&w[wg_off[k]]) : 0.f;
    {
        const float* p0 = in + xci[0] * Hin * Hin + xg_off[0];
        xreg[0].x = xva[0] ? __ldg(p0) : 0.f;
        xreg[0].y = xvb[0] ? __ldg(p0 + 2 * Hin) : 0.f;
        if (t < 32) {
            const float* p1 = in + xci[1] * Hin * Hin + xg_off[1];
            xreg[1].x = xva[1] ? __ldg(p1) : 0.f;
            xreg[1].y = xvb[1] ? __ldg(p1 + 2 * Hin) : 0.f;
        }
    }

    ull acc[NCR][4];
#pragma unroll
    for (int cr = 0; cr < NCR; cr++) {
        float bv = b[zc + co_g * NCR + cr];
        ull bp = pk(bv, bv);
#pragma unroll
        for (int c = 0; c < 4; c++) acc[cr][c] = bp;
    }

    for (int cib = 0; cib < CH; cib += CI_T) {
        __syncthreads();
#pragma unroll
        for (int k = 0; k < WPT; k++)
            if (wok[k]) ws[ws_off[k]] = make_float2(wreg[k], wreg[k]);
        xp[t] = xreg[0];
        if (t < 32) xp[t + 256] = xreg[1];
        __syncthreads();

        if (cib + CI_T < CH) {
            int nb = cib + CI_T;
#pragma unroll
            for (int k = 0; k < WPT; k++)
                if (wok[k]) wreg[k] = __ldg(&w[wg_off[k] + nb * 9]);
            const float* p0 = in + (nb + xci[0]) * Hin * Hin + xg_off[0];
            xreg[0].x = xva[0] ? __ldg(p0) : 0.f;
            xreg[0].y = xvb[0] ? __ldg(p0 + 2 * Hin) : 0.f;
            if (t < 32) {
                const float* p1 = in + (nb + xci[1]) * Hin * Hin + xg_off[1];
                xreg[1].x = xva[1] ? __ldg(p1) : 0.f;
                xreg[1].y = xvb[1] ? __ldg(p1 + 2 * Hin) : 0.f;
            }
        }

#pragma unroll
        for (int ci = 0; ci < CI_T; ci++) {
#pragma unroll
            for (int di = 0; di < 3; di++) {
                const ulonglong2* xr =
                    (const ulonglong2*)&xp[ci * 72 + (rp + di) * 18 + cg * 4];
                ulonglong2 q0 = xr[0];
                ulonglong2 q1 = xr[1];
                ulonglong2 q2 = xr[2];
                ull xv[6] = {q0.x, q0.y, q1.x, q1.y, q2.x, q2.y};
#pragma unroll
                for (int dj = 0; dj < 3; dj++) {
#pragma unroll
                    for (int cr = 0; cr < NCR; cr++) {
                        ull wp = *(const ull*)&ws[(co_g * NCR + cr) * WS_STRIDE
                                                  + ci * 9 + di * 3 + dj];
                        fma2(acc[cr][0], wp, xv[dj + 0]);
                        fma2(acc[cr][1], wp, xv[dj + 1]);
                        fma2(acc[cr][2], wp, xv[dj + 2]);
                        fma2(acc[cr][3], wp, xv[dj + 3]);
                    }
                }
            }
        }
    }

    int r0 = i0 + rp, r1 = i0 + rp + 2;
    int colb = j0 + cg * 4;
#pragma unroll
    for (int cr = 0; cr < NCR; cr++) {
        long pb = (long)(zc + co_g * NCR + cr) * Hout * Hout;
#pragma unroll
        for (int c = 0; c < 4; c++) {
            float2 v = up(acc[cr][c]);
            int col = colb + c;
            if (col < Hout) {
                if (r0 < Hout) out[pb + (long)r0 * Hout + col] = fmaxf(v.x, 0.f);
                if (r1 < Hout) out[pb + (long)r1 * Hout + col] = fmaxf(v.y, 0.f);
            }
        }
    }
}

// ---------------- GEMV partials (DRAM-bound), chunk-ranged ----------------
__global__ void __launch_bounds__(256) gemv_kernel(
    const float* __restrict__ flat, const float* __restrict__ lw,
    float* __restrict__ part, int cbase) {
    __shared__ __align__(16) float sx[GCHUNK];
    int bc = blockIdx.x + cbase;
    long base = (long)bc * GCHUNK;
    int n = FEAT - base;
    if (n > GCHUNK) n = GCHUNK;
    int n4 = n >> 2;

    const float4* xg  = (const float4*)(flat + base);
    float4*       sx4 = (float4*)sx;
    for (int k = threadIdx.x; k < n4; k += 256) sx4[k] = xg[k];
    __syncthreads();

    int wid  = threadIdx.x >> 5;
    int lane = threadIdx.x & 31;
    int rbase = blockIdx.y * 128 + wid * 16;

    for (int g = 0; g < 4; g++) {
        int o = rbase + g * 4;
        const float4* w0 = (const float4*)(lw + (size_t)(o + 0) * FEAT + base);
        const float4* w1 = (const float4*)(lw + (size_t)(o + 1) * FEAT + base);
        const float4* w2 = (const float4*)(lw + (size_t)(o + 2) * FEAT + base);
        const float4* w3 = (const float4*)(lw + (size_t)(o + 3) * FEAT + base);
        float s0 = 0.f, s1 = 0.f, s2 = 0.f, s3 = 0.f;
        for (int k = lane; k < n4; k += 128) {
            float4 a[4][4];
#pragma unroll
            for (int j = 0; j < 4; j++) {
                int kk = k + 32 * j;
                a[0][j] = __ldcs(&w0[kk]);
                a[1][j] = __ldcs(&w1[kk]);
                a[2][j] = __ldcs(&w2[kk]);
                a[3][j] = __ldcs(&w3[kk]);
            }
#pragma unroll
            for (int j = 0; j < 4; j++) {
                float4 xv = sx4[k + 32 * j];
                s0 = fmaf(a[0][j].x, xv.x, s0); s0 = fmaf(a[0][j].y, xv.y, s0);
                s0 = fmaf(a[0][j].z, xv.z, s0); s0 = fmaf(a[0][j].w, xv.w, s0);
                s1 = fmaf(a[1][j].x, xv.x, s1); s1 = fmaf(a[1][j].y, xv.y, s1);
                s1 = fmaf(a[1][j].z, xv.z, s1); s1 = fmaf(a[1][j].w, xv.w, s1);
                s2 = fmaf(a[2][j].x, xv.x, s2); s2 = fmaf(a[2][j].y, xv.y, s2);
                s2 = fmaf(a[2][j].z, xv.z, s2); s2 = fmaf(a[2][j].w, xv.w, s2);
                s3 = fmaf(a[3][j].x, xv.x, s3); s3 = fmaf(a[3][j].y, xv.y, s3);
                s3 = fmaf(a[3][j].z, xv.z, s3); s3 = fmaf(a[3][j].w, xv.w, s3);
            }
        }
#pragma unroll
        for (int off = 16; off; off >>= 1) {
            s0 += __shfl_xor_sync(0xffffffffu, s0, off);
            s1 += __shfl_xor_sync(0xffffffffu, s1, off);
            s2 += __shfl_xor_sync(0xffffffffu, s2, off);
            s3 += __shfl_xor_sync(0xffffffffu, s3, off);
        }
        if (lane == 0) {
            part[bc * OUTD + o + 0] = s0;
            part[bc * OUTD + o + 1] = s1;
            part[bc * OUTD + o + 2] = s2;
            part[bc * OUTD + o + 3] = s3;
        }
    }
}

// ---------------- parallel deterministic reduce + bias ----------------
__global__ void reduce_kernel(const float* __restrict__ part,
                              const float* __restrict__ lb,
                              float* __restrict__ out) {
    int o = blockIdx.x * 8 + (threadIdx.x >> 5);
    int lane = threadIdx.x & 31;
    float s = 0.f;
    for (int c = lane; c < NBLK; c += 32) s += part[c * OUTD + o];
#pragma unroll
    for (int off = 16; off; off >>= 1)
        s += __shfl_xor_sync(0xffffffffu, s, off);
    if (lane == 0) out[o] = lb[o] + s;
}

// ---------------- launch: 2-stream pipelined conv2 || gemv ----------------
extern "C" void kernel_launch(void* const* d_in, const int* in_sizes, int n_in,
                              void* d_out, int out_size) {
    const int*   x      = (const int*)  d_in[0];
    const float* cat_w  = (const float*)d_in[1];
    const float* cat_b  = (const float*)d_in[2];
    const float* conv_w = (const float*)d_in[3];
    const float* conv_b = (const float*)d_in[4];
    const float* lin_w  = (const float*)d_in[5];
    const float* lin_b  = (const float*)d_in[6];
    float* out = (float*)d_out;

    float *y0, *y1, *y2, *part;
    cudaGetSymbolAddress((void**)&y0,   g_y0);
    cudaGetSymbolAddress((void**)&y1,   g_y1);
    cudaGetSymbolAddress((void**)&y2,   g_y2);
    cudaGetSymbolAddress((void**)&part, g_part);

    cudaStream_t s1;
    cudaStreamCreateWithFlags(&s1, cudaStreamNonBlocking);
    cudaEvent_t ev[4], ej;
    for (int q = 0; q < 4; q++)
        cudaEventCreateWithFlags(&ev[q], cudaEventDisableTiming);
    cudaEventCreateWithFlags(&ej, cudaEventDisableTiming);

    dim3 gA((H0 * H0 + 127) / 128, NPC);
    piece_conv<<<gA, 128>>>(x, cat_w, cat_b, y0);

    // conv1: 64 Cout/block, z=2
    dim3 g1((H1 + 15) / 16, (H1 + 3) / 4, 2);
    conv3x3<2><<<g1, 256>>>(y0, conv_w, conv_b, y1, H0, H1, 0);

    // conv2: 4 quarter launches, 32 Cout each; events mark completion
    dim3 g2((H2 + 15) / 16, (H2 + 3) / 4, 1);
    for (int q = 0; q < 4; q++) {
        conv3x3<1><<<g2, 256>>>(y1, conv_w, conv_b, y2, H1, H2, 32 * q);
        cudaEventRecord(ev[q], 0);
    }

    // gemv parts on s1; part p reads features entirely within channels
    // produced by quarters 0..p  (chunk boundaries: 63*4096=258048 <= 259200,
    // 126*4096=516096 <= 518400, 189*4096=774144 <= 777600).
    const int cb[5] = {0, 63, 126, 189, NBLK};
    for (int p = 0; p < 4; p++) {
        cudaStreamWaitEvent(s1, ev[p], 0);
        dim3 gg(cb[p + 1] - cb[p], 2);
        gemv_kernel<<<gg, 256, 0, s1>>>(y2, lin_w, part, cb[p]);
    }
    reduce_kernel<<<32, 256, 0, s1>>>(part, lin_b, out);
    cudaEventRecord(ej, s1);
    cudaStreamWaitEvent(0, ej, 0);
}

// round 11
// speedup vs baseline: 1.5230x; 1.5230x over previous
#include <cuda_runtime.h>

// ---------------- problem constants ----------------
#define NPC   16
#define FBP   8
#define CH    128
#define HH    96
#define H0    94          // after piece conv
#define H1    92          // after conv #1
#define H2    90          // after conv #2
#define FEAT  (CH*H2*H2)  // 1,036,800
#define OUTD  256
#define GCHUNK 4096
#define NBLK  ((FEAT + GCHUNK - 1) / GCHUNK)   // 254

typedef unsigned long long ull;

// ---------------- scratch (no allocation allowed) ----------------
__device__ float g_y0[CH * H0 * H0];
__device__ float g_y1[CH * H1 * H1];
__device__ float g_y2[CH * H2 * H2];
__device__ float g_part[NBLK * OUTD];

// ---------------- packed f32x2 helpers (sm_103a) ----------------
__device__ __forceinline__ ull pk(float lo, float hi) {
    ull r;
    asm("mov.b64 %0, {%1, %2};" : "=l"(r) : "f"(lo), "f"(hi));
    return r;
}
__device__ __forceinline__ void fma2(ull &d, ull a, ull b) {
    asm("fma.rn.f32x2 %0, %1, %2, %0;" : "+l"(d) : "l"(a), "l"(b));
}
__device__ __forceinline__ float2 up(ull v) {
    float x, y;
    asm("mov.b64 {%0, %1}, %2;" : "=f"(x), "=f"(y) : "l"(v));
    return make_float2(x, y);
}

// ---------------- kernel 1: grouped piece conv + bias + relu ----------------
__global__ void piece_conv(const int* __restrict__ x, const float* __restrict__ cw,
                           const float* __restrict__ cb, float* __restrict__ y0) {
    __shared__ float sw[72];
    __shared__ float sb[8];
    int p = blockIdx.y;
    if (threadIdx.x < 72) sw[threadIdx.x] = cw[p * 72 + threadIdx.x];
    if (threadIdx.x < 8)  sb[threadIdx.x] = cb[p * 8 + threadIdx.x];
    __syncthreads();
    int pix = blockIdx.x * blockDim.x + threadIdx.x;
    if (pix >= H0 * H0) return;
    int i = pix / H0, j = pix % H0;
    float acc[FBP];
#pragma unroll
    for (int f = 0; f < FBP; f++) acc[f] = sb[f];
#pragma unroll
    for (int di = 0; di < 3; di++) {
#pragma unroll
        for (int dj = 0; dj < 3; dj++) {
            int v = x[(i + di) * HH + (j + dj)];
            if (v == p) {
#pragma unroll
                for (int f = 0; f < FBP; f++) acc[f] += sw[f * 9 + di * 3 + dj];
            }
        }
    }
#pragma unroll
    for (int f = 0; f < FBP; f++)
        y0[(p * FBP + f) * (H0 * H0) + pix] = fmaxf(acc[f], 0.f);
}

// ---------------- kernel 2/3: 128->128 3x3 VALID conv + bias + relu ----------------
// Tile: 4 rows x 16 cols output, 64 Cout per block (z = Cout half). 256 threads.
// Thread owns 2 Cout x (2 row-paired f32x2) x 4 cols = 16 output px.
// Row-paired f32x2 layout -> zero pack instructions in the inner loop.
// DOUBLE-BUFFERED SMEM: one __syncthreads per cib iteration; staging stores
// + next-next prefetch LDGs overlap the FMA2 compute phase.
#define CI_T 4
#define NITER (CH / CI_T)   // 32
#define WS_STRIDE 37        // float2 per local-Cout row (36 used + 1 pad)
__global__ void __launch_bounds__(256, 2) conv3x3(
    const float* __restrict__ in, const float* __restrict__ w,
    const float* __restrict__ b, float* __restrict__ out,
    int Hin, int Hout) {
    __shared__ __align__(16) float2 ws[2][64 * WS_STRIDE];   // 2 x 18.9 KB
    __shared__ __align__(16) float2 xp[2][CI_T * 4 * 18];    // 2 x 2.3 KB

    int t = threadIdx.x;
    int co_g = t >> 3;                // 0..31 -> 2 Cout each
    int pg   = t & 7;
    int rp   = pg & 1;                // row-pair select: rows (rp, rp+2)
    int cg   = pg >> 1;               // 0..3 -> 4 cols each
    int i0 = blockIdx.y * 4, j0 = blockIdx.x * 16;
    int zc = blockIdx.z * 64;

    // ---- constant per-thread staging maps ----
    // weights: 64*36 = 2304 scalars = exactly 9 per thread
    int wg_off[9], ws_off[9];
#pragma unroll
    for (int k = 0; k < 9; k++) {
        int idx = t + 256 * k;
        int lc = idx / 36, r = idx - lc * 36;
        int ci = r / 9,   d = r - ci * 9;
        wg_off[k] = ((zc + lc) * CH + ci) * 9 + d;   // + cib*9 at load time
        ws_off[k] = lc * WS_STRIDE + r;
    }
    // x: 4*4*18 = 288 float2 entries; entry idx = t (all) and t+256 (t<32)
    int xg_off[2], xci[2];
    unsigned char xva[2], xvb[2];
#pragma unroll
    for (int e = 0; e < 2; e++) {
        int idx = t + 256 * e;
        int ci = idx / 72, rem = idx - ci * 72;
        int rr = rem / 18, c = rem - rr * 18;
        int gi = i0 + rr, gj = j0 + c;
        xci[e] = ci;
        xg_off[e] = gi * Hin + gj;
        xva[e] = (gi < Hin && gj < Hin);
        xvb[e] = (gi + 2 < Hin && gj < Hin);
    }

    float  wreg[9];
    float2 xreg[2];

    // prologue: load tile 0, store into buffer 0, start loading tile 1
#pragma unroll
    for (int k = 0; k < 9; k++) wreg[k] = __ldg(&w[wg_off[k]]);
    {
        const float* p0 = in + xci[0] * Hin * Hin + xg_off[0];
        xreg[0].x = xva[0] ? __ldg(p0) : 0.f;
        xreg[0].y = xvb[0] ? __ldg(p0 + 2 * Hin) : 0.f;
        if (t < 32) {
            const float* p1 = in + xci[1] * Hin * Hin + xg_off[1];
            xreg[1].x = xva[1] ? __ldg(p1) : 0.f;
            xreg[1].y = xvb[1] ? __ldg(p1 + 2 * Hin) : 0.f;
        }
    }
#pragma unroll
    for (int k = 0; k < 9; k++)
        ws[0][ws_off[k]] = make_float2(wreg[k], wreg[k]);
    xp[0][t] = xreg[0];
    if (t < 32) xp[0][t + 256] = xreg[1];
    // prefetch tile 1 (cib = CI_T)
    {
        int nb = CI_T;
#pragma unroll
        for (int k = 0; k < 9; k++) wreg[k] = __ldg(&w[wg_off[k] + nb * 9]);
        const float* p0 = in + (nb + xci[0]) * Hin * Hin + xg_off[0];
        xreg[0].x = xva[0] ? __ldg(p0) : 0.f;
        xreg[0].y = xvb[0] ? __ldg(p0 + 2 * Hin) : 0.f;
        if (t < 32) {
            const float* p1 = in + (nb + xci[1]) * Hin * Hin + xg_off[1];
            xreg[1].x = xva[1] ? __ldg(p1) : 0.f;
            xreg[1].y = xvb[1] ? __ldg(p1 + 2 * Hin) : 0.f;
        }
    }
    __syncthreads();

    ull acc[2][4];
#pragma unroll
    for (int cr = 0; cr < 2; cr++) {
        float bv = b[zc + co_g * 2 + cr];
        ull bp = pk(bv, bv);
#pragma unroll
        for (int c = 0; c < 4; c++) acc[cr][c] = bp;
    }

    for (int i = 0; i < NITER; i++) {
        int cur = i & 1, nxt = cur ^ 1;

        // stage tile i+1 into the other buffer (regs hold it already)
        if (i + 1 < NITER) {
#pragma unroll
            for (int k = 0; k < 9; k++)
                ws[nxt][ws_off[k]] = make_float2(wreg[k], wreg[k]);
            xp[nxt][t] = xreg[0];
            if (t < 32) xp[nxt][t + 256] = xreg[1];
        }
        // prefetch tile i+2 into regs (LDGs fly under the compute below)
        if (i + 2 < NITER) {
            int nb = (i + 2) * CI_T;
#pragma unroll
            for (int k = 0; k < 9; k++)
                wreg[k] = __ldg(&w[wg_off[k] + nb * 9]);
            const float* p0 = in + (nb + xci[0]) * Hin * Hin + xg_off[0];
            xreg[0].x = xva[0] ? __ldg(p0) : 0.f;
            xreg[0].y = xvb[0] ? __ldg(p0 + 2 * Hin) : 0.f;
            if (t < 32) {
                const float* p1 = in + (nb + xci[1]) * Hin * Hin + xg_off[1];
                xreg[1].x = xva[1] ? __ldg(p1) : 0.f;
                xreg[1].y = xvb[1] ? __ldg(p1 + 2 * Hin) : 0.f;
            }
        }

        // compute from current buffer
#pragma unroll
        for (int ci = 0; ci < CI_T; ci++) {
#pragma unroll
            for (int di = 0; di < 3; di++) {
                const ulonglong2* xr =
                    (const ulonglong2*)&xp[cur][ci * 72 + (rp + di) * 18 + cg * 4];
                ulonglong2 q0 = xr[0];
                ulonglong2 q1 = xr[1];
                ulonglong2 q2 = xr[2];
                ull xv[6] = {q0.x, q0.y, q1.x, q1.y, q2.x, q2.y};
#pragma unroll
                for (int dj = 0; dj < 3; dj++) {
#pragma unroll
                    for (int cr = 0; cr < 2; cr++) {
                        ull wp = *(const ull*)&ws[cur][(co_g * 2 + cr) * WS_STRIDE
                                                      + ci * 9 + di * 3 + dj];
                        fma2(acc[cr][0], wp, xv[dj + 0]);
                        fma2(acc[cr][1], wp, xv[dj + 1]);
                        fma2(acc[cr][2], wp, xv[dj + 2]);
                        fma2(acc[cr][3], wp, xv[dj + 3]);
                    }
                }
            }
        }
        __syncthreads();
    }

    // write out: rows (i0+rp, i0+rp+2), cols j0+cg*4 .. +3
    int r0 = i0 + rp, r1 = i0 + rp + 2;
    int colb = j0 + cg * 4;
#pragma unroll
    for (int cr = 0; cr < 2; cr++) {
        long pb = (long)(zc + co_g * 2 + cr) * Hout * Hout;
#pragma unroll
        for (int c = 0; c < 4; c++) {
            float2 v = up(acc[cr][c]);
            int col = colb + c;
            if (col < Hout) {
                if (r0 < Hout) out[pb + (long)r0 * Hout + col] = fmaxf(v.x, 0.f);
                if (r1 < Hout) out[pb + (long)r1 * Hout + col] = fmaxf(v.y, 0.f);
            }
        }
    }
}

// ---------------- kernel 4: GEMV partials (DRAM-bound, ~80% of peak) ----------------
__global__ void __launch_bounds__(256) gemv_kernel(
    const float* __restrict__ flat, const float* __restrict__ lw,
    float* __restrict__ part) {
    __shared__ __align__(16) float sx[GCHUNK];
    int bc = blockIdx.x;
    long base = (long)bc * GCHUNK;
    int n = FEAT - base;
    if (n > GCHUNK) n = GCHUNK;
    int n4 = n >> 2;

    const float4* xg  = (const float4*)(flat + base);
    float4*       sx4 = (float4*)sx;
    for (int k = threadIdx.x; k < n4; k += 256) sx4[k] = xg[k];
    __syncthreads();

    int wid  = threadIdx.x >> 5;
    int lane = threadIdx.x & 31;
    int rbase = blockIdx.y * 128 + wid * 16;

    for (int g = 0; g < 4; g++) {
        int o = rbase + g * 4;
        const float4* w0 = (const float4*)(lw + (size_t)(o + 0) * FEAT + base);
        const float4* w1 = (const float4*)(lw + (size_t)(o + 1) * FEAT + base);
        const float4* w2 = (const float4*)(lw + (size_t)(o + 2) * FEAT + base);
        const float4* w3 = (const float4*)(lw + (size_t)(o + 3) * FEAT + base);
        float s0 = 0.f, s1 = 0.f, s2 = 0.f, s3 = 0.f;
        for (int k = lane; k < n4; k += 128) {
            float4 a[4][4];
#pragma unroll
            for (int j = 0; j < 4; j++) {
                int kk = k + 32 * j;
                a[0][j] = __ldcs(&w0[kk]);
                a[1][j] = __ldcs(&w1[kk]);
                a[2][j] = __ldcs(&w2[kk]);
                a[3][j] = __ldcs(&w3[kk]);
            }
#pragma unroll
            for (int j = 0; j < 4; j++) {
                float4 xv = sx4[k + 32 * j];
                s0 = fmaf(a[0][j].x, xv.x, s0); s0 = fmaf(a[0][j].y, xv.y, s0);
                s0 = fmaf(a[0][j].z, xv.z, s0); s0 = fmaf(a[0][j].w, xv.w, s0);
                s1 = fmaf(a[1][j].x, xv.x, s1); s1 = fmaf(a[1][j].y, xv.y, s1);
                s1 = fmaf(a[1][j].z, xv.z, s1); s1 = fmaf(a[1][j].w, xv.w, s1);
                s2 = fmaf(a[2][j].x, xv.x, s2); s2 = fmaf(a[2][j].y, xv.y, s2);
                s2 = fmaf(a[2][j].z, xv.z, s2); s2 = fmaf(a[2][j].w, xv.w, s2);
                s3 = fmaf(a[3][j].x, xv.x, s3); s3 = fmaf(a[3][j].y, xv.y, s3);
                s3 = fmaf(a[3][j].z, xv.z, s3); s3 = fmaf(a[3][j].w, xv.w, s3);
            }
        }
#pragma unroll
        for (int off = 16; off; off >>= 1) {
            s0 += __shfl_xor_sync(0xffffffffu, s0, off);
            s1 += __shfl_xor_sync(0xffffffffu, s1, off);
            s2 += __shfl_xor_sync(0xffffffffu, s2, off);
            s3 += __shfl_xor_sync(0xffffffffu, s3, off);
        }
        if (lane == 0) {
            part[bc * OUTD + o + 0] = s0;
            part[bc * OUTD + o + 1] = s1;
            part[bc * OUTD + o + 2] = s2;
            part[bc * OUTD + o + 3] = s3;
        }
    }
}

// ---------------- kernel 5: parallel deterministic reduce + bias ----------------
__global__ void reduce_kernel(const float* __restrict__ part,
                              const float* __restrict__ lb,
                              float* __restrict__ out) {
    int o = blockIdx.x * 8 + (threadIdx.x >> 5);
    int lane = threadIdx.x & 31;
    float s = 0.f;
    for (int c = lane; c < NBLK; c += 32) s += part[c * OUTD + o];
#pragma unroll
    for (int off = 16; off; off >>= 1)
        s += __shfl_xor_sync(0xffffffffu, s, off);
    if (lane == 0) out[o] = lb[o] + s;
}

// ---------------- launch (single stream, serial — R9 overlap reverted) ----------------
extern "C" void kernel_launch(void* const* d_in, const int* in_sizes, int n_in,
                              void* d_out, int out_size) {
    const int*   x      = (const int*)  d_in[0];
    const float* cat_w  = (const float*)d_in[1];
    const float* cat_b  = (const float*)d_in[2];
    const float* conv_w = (const float*)d_in[3];
    const float* conv_b = (const float*)d_in[4];
    const float* lin_w  = (const float*)d_in[5];
    const float* lin_b  = (const float*)d_in[6];
    float* out = (float*)d_out;

    float *y0, *y1, *y2, *part;
    cudaGetSymbolAddress((void**)&y0,   g_y0);
    cudaGetSymbolAddress((void**)&y1,   g_y1);
    cudaGetSymbolAddress((void**)&y2,   g_y2);
    cudaGetSymbolAddress((void**)&part, g_part);

    dim3 gA((H0 * H0 + 127) / 128, NPC);
    piece_conv<<<gA, 128>>>(x, cat_w, cat_b, y0);

    dim3 g1((H1 + 15) / 16, (H1 + 3) / 4, 2);
    conv3x3<<<g1, 256>>>(y0, conv_w, conv_b, y1, H0, H1);

    dim3 g2((H2 + 15) / 16, (H2 + 3) / 4, 2);
    conv3x3<<<g2, 256>>>(y1, conv_w, conv_b, y2, H1, H2);

    dim3 gg(NBLK, 2);
    gemv_kernel<<<gg, 256>>>(y2, lin_w, part);
    reduce_kernel<<<32, 256>>>(part, lin_b, out);
}